// round 9
// baseline (speedup 1.0000x reference)
#include <cuda_runtime.h>
#include <math.h>

// ESN: B=256, T=512, D=64, N=512, leak=0.5
// Output: [ X (B,T,N) fp32 ][ X_last (B,N) fp32 ]

#define BB 256
#define TT 512
#define DD 64
#define NN 512
#define LEAK 0.5f
#define NCTA 256       // 8 m-slabs x 32 n-tiles(16 wide); 2 CTAs/SM
#define WBS 1040       // Wb row stride (words): 1040 mod 32 == 16 -> LDS.128 conflict-free
#define NGRP 8
#define HGRP 16        // CTAs per half-group counter

typedef unsigned long long ull;

__device__ unsigned g_cnt[NGRP * 2 * 32];    // 128B-spaced half-group counters
__device__ float g_xt[2][BB][NN];            // tf32-prerounded x_t, double-buffered

__device__ __forceinline__ void fma2(ull &acc, ull a, ull b) {
    asm("fma.rn.f32x2 %0, %1, %2, %0;" : "+l"(acc) : "l"(a), "l"(b));
}
__device__ __forceinline__ float2 unpack2(ull v) {
    float2 r; asm("mov.b64 {%0, %1}, %2;" : "=f"(r.x), "=f"(r.y) : "l"(v)); return r;
}
__device__ __forceinline__ unsigned atom_add_rel(unsigned* p, unsigned v) {
    unsigned r;
    asm volatile("atom.add.release.gpu.global.u32 %0, [%1], %2;"
                 : "=r"(r) : "l"(p), "r"(v) : "memory");
    return r;
}
__device__ __forceinline__ unsigned ld_acq(const unsigned* p) {
    unsigned r;
    asm volatile("ld.acquire.gpu.global.u32 %0, [%1];" : "=r"(r) : "l"(p) : "memory");
    return r;
}
__device__ __forceinline__ float tf32r(float x) {
    unsigned u; asm("cvt.rna.tf32.f32 %0, %1;" : "=r"(u) : "f"(x));
    return __uint_as_float(u);
}
__device__ __forceinline__ void mma8(float &c0, float &c1, float &c2, float &c3,
                                     float a0, float a1, float a2, float a3,
                                     float b0, float b1) {
    asm("mma.sync.aligned.m16n8k8.row.col.f32.tf32.tf32.f32 "
        "{%0,%1,%2,%3},{%4,%5,%6,%7},{%8,%9},{%0,%1,%2,%3};"
        : "+f"(c0), "+f"(c1), "+f"(c2), "+f"(c3)
        : "r"(__float_as_uint(a0)), "r"(__float_as_uint(a1)),
          "r"(__float_as_uint(a2)), "r"(__float_as_uint(a3)),
          "r"(__float_as_uint(b0)), "r"(__float_as_uint(b1)));
}

// ---------------------------------------------------------------------------
// Projection: U = inputs@W_in + b_in; x0 = leak*tanh(U0) at t=0 (also stored
// tf32-rounded into g_xt[0]). Block (0,0) resets the half-group counters.
// ---------------------------------------------------------------------------
__global__ __launch_bounds__(128) void proj_kernel(
    const float* __restrict__ inp, const float* __restrict__ Win,
    const float* __restrict__ bin, float* __restrict__ X)
{
    __shared__ __align__(16) float Ash[DD][36];
    __shared__ __align__(16) float Wd[DD][64];

    const int tid = threadIdx.x;
    const int m0 = blockIdx.x * 32;
    const int n0 = blockIdx.y * 32;

    if (blockIdx.x == 0 && blockIdx.y == 0 && tid < NGRP * 2)
        g_cnt[tid * 32] = 0u;

    {
        int c = tid & 63, mi = tid >> 6;
        #pragma unroll
        for (int j = 0; j < 16; j++) {
            int m = j * 2 + mi;
            Ash[c][m] = inp[(m0 + m) * DD + c];
        }
    }
    {
        int n = tid & 31, kw = tid >> 5;
        #pragma unroll
        for (int j = 0; j < 16; j++) {
            int k = j * 4 + kw;
            float w = Win[k * NN + n0 + n];
            Wd[k][2 * n] = w; Wd[k][2 * n + 1] = w;
        }
    }
    __syncthreads();

    const int tx = tid & 7;
    const int ty = tid >> 3;
    ull acc0 = 0, acc1 = 0, acc2 = 0, acc3 = 0;

    #pragma unroll
    for (int k = 0; k < DD; k++) {
        ull a = *(const ull*)&Ash[k][2 * ty];
        const ulonglong2* bp = (const ulonglong2*)&Wd[k][8 * tx];
        ulonglong2 b01 = bp[0], b23 = bp[1];
        fma2(acc0, a, b01.x); fma2(acc1, a, b01.y);
        fma2(acc2, a, b23.x); fma2(acc3, a, b23.y);
    }

    const int r0 = m0 + 2 * ty;
    const int t0 = r0 & (TT - 1);
    const int nb = n0 + 4 * tx;
    ull accs[4] = {acc0, acc1, acc2, acc3};
    #pragma unroll
    for (int c = 0; c < 4; c++) {
        float2 v = unpack2(accs[c]);
        int n = nb + c;
        float b = bin[n];
        float u0 = v.x + b;
        float u1 = v.y + b;
        if (t0 == 0) {
            float x0 = LEAK * tanhf(u0);
            X[(size_t)r0 * NN + n] = x0;
            g_xt[0][r0 >> 9][n] = tf32r(x0);
        } else {
            X[(size_t)r0 * NN + n] = u0;
        }
        X[(size_t)(r0 + 1) * NN + n] = u1;
    }
}

// ---------------------------------------------------------------------------
// Persistent tensor-core recurrence: 256 CTAs = 8 m-slabs x 32 n-tiles(16),
// 2 CTAs/SM (co-residents in different groups -> slack overlap).
// 256 threads = 8 warps = 2 m-halves (wm) x 4 k-quarters (kq).
// A-fragments loaded directly from g_xt via __ldcg (no smem staging).
// B quad-packed in smem: Wb[gid][k8][tig][4] = {W[n0+gid][k], W[..][k+4],
// W[n0+gid+8][k], W[..][k+4]} -> one LDS.128 per k8 per warp.
// ---------------------------------------------------------------------------
__global__ __launch_bounds__(256, 2) void esn_mma(
    float* __restrict__ X, const float* __restrict__ Wres,
    const float* __restrict__ bres, float* __restrict__ xlast)
{
    extern __shared__ __align__(16) float smem[];
    float* Wb  = smem;                // [8][WBS]
    float* Rsm = smem + 8 * WBS;      // [2][4][32][8] partials

    const int tid  = threadIdx.x;
    const int warp = tid >> 5, lane = tid & 31;
    const int wm   = warp >> 2;       // m-half
    const int kq   = warp & 3;        // k-quarter
    const int gid  = lane >> 2, tig = lane & 3;
    const int bx   = blockIdx.x;
    const int grp  = bx >> 5;         // 0..7 m-slab
    const int nt   = bx & 31;         // 0..31 n-tile (16 wide)
    const int m0   = grp * 32;
    const int n0   = nt * 16;
    const int TN   = TT * NN;

    unsigned* cntA = &g_cnt[(grp * 2 + 0) * 32];
    unsigned* cntB = &g_cnt[(grp * 2 + 1) * 32];
    unsigned* own  = &g_cnt[(grp * 2 + (nt >> 4)) * 32];

    // ---- stage quad-packed tf32 W once ----
    for (int idx = tid; idx < 8 * 64 * 4; idx += 256) {
        int g   = idx >> 8;          // 0..7
        int rem = idx & 255;
        int k8  = rem >> 2;          // 0..63
        int tg  = rem & 3;
        int k0  = 8 * k8 + tg;
        float* d = Wb + g * WBS + k8 * 16 + tg * 4;
        d[0] = tf32r(Wres[(size_t)k0 * NN + n0 + g]);
        d[1] = tf32r(Wres[(size_t)(k0 + 4) * NN + n0 + g]);
        d[2] = tf32r(Wres[(size_t)k0 * NN + n0 + g + 8]);
        d[3] = tf32r(Wres[(size_t)(k0 + 4) * NN + n0 + g + 8]);
    }

    const int r0 = m0 + 16 * wm + gid;        // rows r0, r0+8
    const int cb = n0 + 2 * tig;              // cols cb,cb+1; +8 for n8=1
    const float* wbp = Wb + gid * WBS + kq * 256 + tig * 4;
    float* rme = Rsm + ((size_t)(wm * 4 + kq) * 32 + lane) * 8;
    const int koff = kq * 128;

    const float2 br0 = *(const float2*)&bres[cb];
    const float2 br1 = *(const float2*)&bres[cb + 8];

    // register-carried x_prev + U prefetch for t=1 (kq==0 warps)
    float2 p00, p01, p10, p11, u00, u01, u10, u11;
    if (kq == 0) {
        p00 = *(const float2*)&X[(size_t)r0 * TN + cb];
        p01 = *(const float2*)&X[(size_t)r0 * TN + cb + 8];
        p10 = *(const float2*)&X[(size_t)(r0 + 8) * TN + cb];
        p11 = *(const float2*)&X[(size_t)(r0 + 8) * TN + cb + 8];
        size_t b1 = (size_t)r0 * TN + (size_t)1 * NN + cb;
        u00 = __ldcg((const float2*)&X[b1]);
        u01 = __ldcg((const float2*)&X[b1 + 8]);
        u10 = __ldcg((const float2*)&X[b1 + (size_t)8 * TN]);
        u11 = __ldcg((const float2*)&X[b1 + (size_t)8 * TN + 8]);
    }
    __syncthreads();   // Wb ready

    for (int t = 1; t < TT; t++) {
        const int par = (t - 1) & 1;
        const float* ar0 = &g_xt[par][r0][koff];
        const float* ar1 = &g_xt[par][r0 + 8][koff];

        // ---- GEMM over this warp's k-quarter: A direct from L2, B smem ----
        float h00 = 0.f, h01 = 0.f, h02 = 0.f, h03 = 0.f;
        float h10 = 0.f, h11 = 0.f, h12 = 0.f, h13 = 0.f;

        #pragma unroll 4
        for (int j = 0; j < 16; j++) {
            int kk = j * 8 + tig;
            float a0 = __ldcg(ar0 + kk);
            float a2 = __ldcg(ar0 + kk + 4);
            float a1 = __ldcg(ar1 + kk);
            float a3 = __ldcg(ar1 + kk + 4);
            float4 b = *(const float4*)(wbp + j * 16);
            mma8(h00, h01, h02, h03, a0, a1, a2, a3, b.x, b.y);
            mma8(h10, h11, h12, h13, a0, a1, a2, a3, b.z, b.w);
        }

        // ---- k-quarter reduction via smem ----
        if (kq != 0) {
            *(float4*)(rme + 0) = make_float4(h00, h01, h02, h03);
            *(float4*)(rme + 4) = make_float4(h10, h11, h12, h13);
        }
        __syncthreads();

        size_t base = (size_t)r0 * TN + (size_t)t * NN + cb;
        float2 o00, o01, o10, o11;
        if (kq == 0) {
            float s0 = h00, s1 = h01, s2 = h02, s3 = h03;
            float s4 = h10, s5 = h11, s6 = h12, s7 = h13;
            const float* rb = Rsm + ((size_t)(wm * 4) * 32 + lane) * 8;
            #pragma unroll
            for (int qq = 1; qq < 4; qq++) {
                float4 v0 = *(const float4*)(rb + (size_t)qq * 32 * 8 + 0);
                float4 v1 = *(const float4*)(rb + (size_t)qq * 32 * 8 + 4);
                s0 += v0.x; s1 += v0.y; s2 += v0.z; s3 += v0.w;
                s4 += v1.x; s5 += v1.y; s6 += v1.z; s7 += v1.w;
            }

            o00.x = 0.5f * p00.x + 0.5f * tanhf(u00.x + s0 + br0.x);
            o00.y = 0.5f * p00.y + 0.5f * tanhf(u00.y + s1 + br0.y);
            o10.x = 0.5f * p10.x + 0.5f * tanhf(u10.x + s2 + br0.x);
            o10.y = 0.5f * p10.y + 0.5f * tanhf(u10.y + s3 + br0.y);
            o01.x = 0.5f * p01.x + 0.5f * tanhf(u01.x + s4 + br1.x);
            o01.y = 0.5f * p01.y + 0.5f * tanhf(u01.y + s5 + br1.y);
            o11.x = 0.5f * p11.x + 0.5f * tanhf(u11.x + s6 + br1.x);
            o11.y = 0.5f * p11.y + 0.5f * tanhf(u11.y + s7 + br1.y);
            p00 = o00; p01 = o01; p10 = o10; p11 = o11;

            // peers only need g_xt -> store it first
            float* xt  = &g_xt[t & 1][r0][cb];
            float* xt8 = &g_xt[t & 1][r0 + 8][cb];
            xt[0]  = tf32r(o00.x); xt[1]  = tf32r(o00.y);
            xt[8]  = tf32r(o01.x); xt[9]  = tf32r(o01.y);
            xt8[0] = tf32r(o10.x); xt8[1] = tf32r(o10.y);
            xt8[8] = tf32r(o11.x); xt8[9] = tf32r(o11.y);
        }

        if (t < TT - 1) {
            __syncthreads();                       // all g_xt stores done
            if (tid == 0) atom_add_rel(own, 1u);   // release ASAP

            // off-critical-path: X store + next U prefetch overlap the poll
            if (kq == 0) {
                *(float2*)&X[base]                      = o00;
                *(float2*)&X[base + 8]                  = o01;
                *(float2*)&X[base + (size_t)8 * TN]     = o10;
                *(float2*)&X[base + (size_t)8 * TN + 8] = o11;
                size_t bn = base + NN;
                u00 = __ldcg((const float2*)&X[bn]);
                u01 = __ldcg((const float2*)&X[bn + 8]);
                u10 = __ldcg((const float2*)&X[bn + (size_t)8 * TN]);
                u11 = __ldcg((const float2*)&X[bn + (size_t)8 * TN + 8]);
            }
            if (tid == 0) {
                unsigned target = (unsigned)t * HGRP;
                while (ld_acq(cntA) < target) { }
                while (ld_acq(cntB) < target) { }
            }
            __syncthreads();
        } else if (kq == 0) {
            *(float2*)&X[base]                      = o00;
            *(float2*)&X[base + 8]                  = o01;
            *(float2*)&X[base + (size_t)8 * TN]     = o10;
            *(float2*)&X[base + (size_t)8 * TN + 8] = o11;
            *(float2*)&xlast[(size_t)r0 * NN + cb]           = o00;
            *(float2*)&xlast[(size_t)r0 * NN + cb + 8]       = o01;
            *(float2*)&xlast[(size_t)(r0 + 8) * NN + cb]     = o10;
            *(float2*)&xlast[(size_t)(r0 + 8) * NN + cb + 8] = o11;
        }
    }
}

extern "C" void kernel_launch(void* const* d_in, const int* in_sizes, int n_in,
                              void* d_out, int out_size)
{
    const float* inp  = (const float*)d_in[0];
    const float* Win  = (const float*)d_in[1];
    const float* bin  = (const float*)d_in[2];
    const float* Wres = (const float*)d_in[3];
    const float* bres = (const float*)d_in[4];

    float* X = (float*)d_out;                       // (B, T, N)
    float* xlast = X + (size_t)BB * TT * NN;        // (B, N)

    const int smem_bytes = (8 * WBS + 2 * 4 * 32 * 8) * sizeof(float);  // 41472
    cudaFuncSetAttribute(esn_mma, cudaFuncAttributeMaxDynamicSharedMemorySize, smem_bytes);

    dim3 g1(BB * TT / 32, NN / 32);
    proj_kernel<<<g1, 128>>>(inp, Win, bin, X);

    esn_mma<<<NCTA, 256, smem_bytes>>>(X, Wres, bres, xlast);
}

// round 10
// speedup vs baseline: 1.3409x; 1.3409x over previous
#include <cuda_runtime.h>
#include <math.h>

// ESN: B=256, T=512, D=64, N=512, leak=0.5
// Output: [ X (B,T,N) fp32 ][ X_last (B,N) fp32 ]

#define BB 256
#define TT 512
#define DD 64
#define NN 512
#define LEAK 0.5f
#define NCTA 256       // 8 m-slabs x 32 n-tiles(16 wide); 2 CTAs/SM
#define AS 516         // Asm row stride (words): conflict-free scalar A loads
#define WBS 1040       // Wb row stride (words)
#define NGRP 8
#define HGRP 16        // CTAs per half-group counter

typedef unsigned long long ull;

__device__ unsigned g_cnt[NGRP * 2 * 32];    // 128B-spaced half-group counters
__device__ float g_xt[2][BB][NN];            // tf32-prerounded x_t, double-buffered

__device__ __forceinline__ void fma2(ull &acc, ull a, ull b) {
    asm("fma.rn.f32x2 %0, %1, %2, %0;" : "+l"(acc) : "l"(a), "l"(b));
}
__device__ __forceinline__ float2 unpack2(ull v) {
    float2 r; asm("mov.b64 {%0, %1}, %2;" : "=f"(r.x), "=f"(r.y) : "l"(v)); return r;
}
__device__ __forceinline__ unsigned atom_add_rel(unsigned* p, unsigned v) {
    unsigned r;
    asm volatile("atom.add.release.gpu.global.u32 %0, [%1], %2;"
                 : "=r"(r) : "l"(p), "r"(v) : "memory");
    return r;
}
__device__ __forceinline__ unsigned ld_acq(const unsigned* p) {
    unsigned r;
    asm volatile("ld.acquire.gpu.global.u32 %0, [%1];" : "=r"(r) : "l"(p) : "memory");
    return r;
}
__device__ __forceinline__ float tf32r(float x) {
    unsigned u; asm("cvt.rna.tf32.f32 %0, %1;" : "=r"(u) : "f"(x));
    return __uint_as_float(u);
}
__device__ __forceinline__ void mma8(float &c0, float &c1, float &c2, float &c3,
                                     float a0, float a1, float a2, float a3,
                                     float b0, float b1) {
    asm("mma.sync.aligned.m16n8k8.row.col.f32.tf32.tf32.f32 "
        "{%0,%1,%2,%3},{%4,%5,%6,%7},{%8,%9},{%0,%1,%2,%3};"
        : "+f"(c0), "+f"(c1), "+f"(c2), "+f"(c3)
        : "r"(__float_as_uint(a0)), "r"(__float_as_uint(a1)),
          "r"(__float_as_uint(a2)), "r"(__float_as_uint(a3)),
          "r"(__float_as_uint(b0)), "r"(__float_as_uint(b1)));
}

// ---------------------------------------------------------------------------
// Projection: U = inputs@W_in + b_in; x0 = leak*tanh(U0) at t=0 (also stored
// tf32-rounded into g_xt[0]). Block (0,0) resets the half-group counters.
// ---------------------------------------------------------------------------
__global__ __launch_bounds__(128) void proj_kernel(
    const float* __restrict__ inp, const float* __restrict__ Win,
    const float* __restrict__ bin, float* __restrict__ X)
{
    __shared__ __align__(16) float Ash[DD][36];
    __shared__ __align__(16) float Wd[DD][64];

    const int tid = threadIdx.x;
    const int m0 = blockIdx.x * 32;
    const int n0 = blockIdx.y * 32;

    if (blockIdx.x == 0 && blockIdx.y == 0 && tid < NGRP * 2)
        g_cnt[tid * 32] = 0u;

    {
        int c = tid & 63, mi = tid >> 6;
        #pragma unroll
        for (int j = 0; j < 16; j++) {
            int m = j * 2 + mi;
            Ash[c][m] = inp[(m0 + m) * DD + c];
        }
    }
    {
        int n = tid & 31, kw = tid >> 5;
        #pragma unroll
        for (int j = 0; j < 16; j++) {
            int k = j * 4 + kw;
            float w = Win[k * NN + n0 + n];
            Wd[k][2 * n] = w; Wd[k][2 * n + 1] = w;
        }
    }
    __syncthreads();

    const int tx = tid & 7;
    const int ty = tid >> 3;
    ull acc0 = 0, acc1 = 0, acc2 = 0, acc3 = 0;

    #pragma unroll
    for (int k = 0; k < DD; k++) {
        ull a = *(const ull*)&Ash[k][2 * ty];
        const ulonglong2* bp = (const ulonglong2*)&Wd[k][8 * tx];
        ulonglong2 b01 = bp[0], b23 = bp[1];
        fma2(acc0, a, b01.x); fma2(acc1, a, b01.y);
        fma2(acc2, a, b23.x); fma2(acc3, a, b23.y);
    }

    const int r0 = m0 + 2 * ty;
    const int t0 = r0 & (TT - 1);
    const int nb = n0 + 4 * tx;
    ull accs[4] = {acc0, acc1, acc2, acc3};
    #pragma unroll
    for (int c = 0; c < 4; c++) {
        float2 v = unpack2(accs[c]);
        int n = nb + c;
        float b = bin[n];
        float u0 = v.x + b;
        float u1 = v.y + b;
        if (t0 == 0) {
            float x0 = LEAK * tanhf(u0);
            X[(size_t)r0 * NN + n] = x0;
            g_xt[0][r0 >> 9][n] = tf32r(x0);
        } else {
            X[(size_t)r0 * NN + n] = u0;
        }
        X[(size_t)(r0 + 1) * NN + n] = u1;
    }
}

// ---------------------------------------------------------------------------
// Persistent tensor-core recurrence: 256 CTAs = 8 m-slabs x 32 n-tiles(16),
// 2 CTAs/SM. 256 threads = 8 warps = 2 m-halves (wm) x 4 k-quarters (kq).
// A staged through smem (coalesced LDG.128 + conflict-free STS/LDS);
// W quad-packed: one LDS.128 per k8 per warp feeds both n8 chains.
// ---------------------------------------------------------------------------
__global__ __launch_bounds__(256, 2) void esn_mma(
    float* __restrict__ X, const float* __restrict__ Wres,
    const float* __restrict__ bres, float* __restrict__ xlast)
{
    extern __shared__ __align__(16) float smem[];
    float* Asm = smem;                  // [32][AS]
    float* Wb  = smem + 32 * AS;        // [8][WBS]
    float* Rsm = Wb + 8 * WBS;          // [2][4][32][8] partials

    const int tid  = threadIdx.x;
    const int warp = tid >> 5, lane = tid & 31;
    const int wm   = warp >> 2;       // m-half
    const int kq   = warp & 3;        // k-quarter
    const int gid  = lane >> 2, tig = lane & 3;
    const int bx   = blockIdx.x;
    const int grp  = bx >> 5;         // 0..7 m-slab
    const int nt   = bx & 31;         // 0..31 n-tile (16 wide)
    const int m0   = grp * 32;
    const int n0   = nt * 16;
    const int TN   = TT * NN;

    unsigned* cntA = &g_cnt[(grp * 2 + 0) * 32];
    unsigned* cntB = &g_cnt[(grp * 2 + 1) * 32];
    unsigned* own  = &g_cnt[(grp * 2 + (nt >> 4)) * 32];

    // ---- stage quad-packed tf32 W once (layout validated in R9) ----
    for (int idx = tid; idx < 8 * 64 * 4; idx += 256) {
        int g   = idx >> 8;
        int rem = idx & 255;
        int k8  = rem >> 2;
        int tg  = rem & 3;
        int k0  = 8 * k8 + tg;
        float* d = Wb + g * WBS + k8 * 16 + tg * 4;
        d[0] = tf32r(Wres[(size_t)k0 * NN + n0 + g]);
        d[1] = tf32r(Wres[(size_t)(k0 + 4) * NN + n0 + g]);
        d[2] = tf32r(Wres[(size_t)k0 * NN + n0 + g + 8]);
        d[3] = tf32r(Wres[(size_t)(k0 + 4) * NN + n0 + g + 8]);
    }

    const int r0 = m0 + 16 * wm + gid;        // rows r0, r0+8
    const int cb = n0 + 2 * tig;              // cols cb,cb+1; +8 for n8=1
    const float* arow0 = Asm + (16 * wm + gid) * AS + kq * 128;
    const float* arow1 = arow0 + 8 * AS;
    const float* wbp = Wb + gid * WBS + kq * 256 + tig * 4;
    float* rme = Rsm + ((size_t)(wm * 4 + kq) * 32 + lane) * 8;

    // staging mapping
    const int sr = tid >> 3;
    const int sg = tid & 7;

    const float2 br0 = *(const float2*)&bres[cb];
    const float2 br1 = *(const float2*)&bres[cb + 8];

    // register-carried x_prev + U prefetch for t=1 (kq==0 warps)
    float2 p00, p01, p10, p11, u00, u01, u10, u11;
    if (kq == 0) {
        p00 = *(const float2*)&X[(size_t)r0 * TN + cb];
        p01 = *(const float2*)&X[(size_t)r0 * TN + cb + 8];
        p10 = *(const float2*)&X[(size_t)(r0 + 8) * TN + cb];
        p11 = *(const float2*)&X[(size_t)(r0 + 8) * TN + cb + 8];
        size_t b1 = (size_t)r0 * TN + (size_t)1 * NN + cb;
        u00 = __ldcg((const float2*)&X[b1]);
        u01 = __ldcg((const float2*)&X[b1 + 8]);
        u10 = __ldcg((const float2*)&X[b1 + (size_t)8 * TN]);
        u11 = __ldcg((const float2*)&X[b1 + (size_t)8 * TN + 8]);
    }

    for (int t = 1; t < TT; t++) {
        // ---- stage A slab from pre-rounded g_xt (coalesced, smem) ----
        {
            const float4* rp = (const float4*)&g_xt[(t - 1) & 1][m0 + sr][0];
            float* dr = Asm + sr * AS;
            #pragma unroll
            for (int j = 0; j < 16; j++) {
                int i4 = sg + 8 * j;
                float4 v = __ldcg(rp + i4);
                *(float4*)(dr + 4 * i4) = v;
            }
        }
        __syncthreads();

        // ---- GEMM over this warp's k-quarter ----
        float h00 = 0.f, h01 = 0.f, h02 = 0.f, h03 = 0.f;
        float h10 = 0.f, h11 = 0.f, h12 = 0.f, h13 = 0.f;

        #pragma unroll 4
        for (int j = 0; j < 16; j++) {
            int kk = j * 8 + tig;
            float a0 = arow0[kk];
            float a2 = arow0[kk + 4];
            float a1 = arow1[kk];
            float a3 = arow1[kk + 4];
            float4 b = *(const float4*)(wbp + j * 16);
            mma8(h00, h01, h02, h03, a0, a1, a2, a3, b.x, b.y);
            mma8(h10, h11, h12, h13, a0, a1, a2, a3, b.z, b.w);
        }

        // ---- k-quarter reduction via smem ----
        if (kq != 0) {
            *(float4*)(rme + 0) = make_float4(h00, h01, h02, h03);
            *(float4*)(rme + 4) = make_float4(h10, h11, h12, h13);
        }
        __syncthreads();

        size_t base = (size_t)r0 * TN + (size_t)t * NN + cb;
        float2 o00, o01, o10, o11;
        if (kq == 0) {
            float s0 = h00, s1 = h01, s2 = h02, s3 = h03;
            float s4 = h10, s5 = h11, s6 = h12, s7 = h13;
            const float* rb = Rsm + ((size_t)(wm * 4) * 32 + lane) * 8;
            #pragma unroll
            for (int qq = 1; qq < 4; qq++) {
                float4 v0 = *(const float4*)(rb + (size_t)qq * 32 * 8 + 0);
                float4 v1 = *(const float4*)(rb + (size_t)qq * 32 * 8 + 4);
                s0 += v0.x; s1 += v0.y; s2 += v0.z; s3 += v0.w;
                s4 += v1.x; s5 += v1.y; s6 += v1.z; s7 += v1.w;
            }

            o00.x = 0.5f * p00.x + 0.5f * tanhf(u00.x + s0 + br0.x);
            o00.y = 0.5f * p00.y + 0.5f * tanhf(u00.y + s1 + br0.y);
            o10.x = 0.5f * p10.x + 0.5f * tanhf(u10.x + s2 + br0.x);
            o10.y = 0.5f * p10.y + 0.5f * tanhf(u10.y + s3 + br0.y);
            o01.x = 0.5f * p01.x + 0.5f * tanhf(u01.x + s4 + br1.x);
            o01.y = 0.5f * p01.y + 0.5f * tanhf(u01.y + s5 + br1.y);
            o11.x = 0.5f * p11.x + 0.5f * tanhf(u11.x + s6 + br1.x);
            o11.y = 0.5f * p11.y + 0.5f * tanhf(u11.y + s7 + br1.y);
            p00 = o00; p01 = o01; p10 = o10; p11 = o11;

            // peers only need g_xt -> store it first
            float* xt  = &g_xt[t & 1][r0][cb];
            float* xt8 = &g_xt[t & 1][r0 + 8][cb];
            xt[0]  = tf32r(o00.x); xt[1]  = tf32r(o00.y);
            xt[8]  = tf32r(o01.x); xt[9]  = tf32r(o01.y);
            xt8[0] = tf32r(o10.x); xt8[1] = tf32r(o10.y);
            xt8[8] = tf32r(o11.x); xt8[9] = tf32r(o11.y);
        }

        if (t < TT - 1) {
            __syncthreads();                       // all g_xt stores done
            if (tid == 0) atom_add_rel(own, 1u);   // release ASAP

            // off-critical-path: X store + next U prefetch overlap the poll
            if (kq == 0) {
                *(float2*)&X[base]                      = o00;
                *(float2*)&X[base + 8]                  = o01;
                *(float2*)&X[base + (size_t)8 * TN]     = o10;
                *(float2*)&X[base + (size_t)8 * TN + 8] = o11;
                size_t bn = base + NN;
                u00 = __ldcg((const float2*)&X[bn]);
                u01 = __ldcg((const float2*)&X[bn + 8]);
                u10 = __ldcg((const float2*)&X[bn + (size_t)8 * TN]);
                u11 = __ldcg((const float2*)&X[bn + (size_t)8 * TN + 8]);
            }
            if (tid == 0) {
                unsigned target = (unsigned)t * HGRP;
                while (ld_acq(cntA) < target) { }
                while (ld_acq(cntB) < target) { }
            }
            __syncthreads();
        } else if (kq == 0) {
            *(float2*)&X[base]                      = o00;
            *(float2*)&X[base + 8]                  = o01;
            *(float2*)&X[base + (size_t)8 * TN]     = o10;
            *(float2*)&X[base + (size_t)8 * TN + 8] = o11;
            *(float2*)&xlast[(size_t)r0 * NN + cb]           = o00;
            *(float2*)&xlast[(size_t)r0 * NN + cb + 8]       = o01;
            *(float2*)&xlast[(size_t)(r0 + 8) * NN + cb]     = o10;
            *(float2*)&xlast[(size_t)(r0 + 8) * NN + cb + 8] = o11;
        }
    }
}

extern "C" void kernel_launch(void* const* d_in, const int* in_sizes, int n_in,
                              void* d_out, int out_size)
{
    const float* inp  = (const float*)d_in[0];
    const float* Win  = (const float*)d_in[1];
    const float* bin  = (const float*)d_in[2];
    const float* Wres = (const float*)d_in[3];
    const float* bres = (const float*)d_in[4];

    float* X = (float*)d_out;                       // (B, T, N)
    float* xlast = X + (size_t)BB * TT * NN;        // (B, N)

    const int smem_bytes = (32 * AS + 8 * WBS + 2 * 4 * 32 * 8) * sizeof(float);  // 107520
    cudaFuncSetAttribute(esn_mma, cudaFuncAttributeMaxDynamicSharedMemorySize, smem_bytes);

    dim3 g1(BB * TT / 32, NN / 32);
    proj_kernel<<<g1, 128>>>(inp, Win, bin, X);

    esn_mma<<<NCTA, 256, smem_bytes>>>(X, Wres, bres, xlast);
}

// round 12
// speedup vs baseline: 1.6260x; 1.2126x over previous
#include <cuda_runtime.h>
#include <math.h>

// ESN: B=256, T=512, D=64, N=512, leak=0.5
// Output: [ X (B,T,N) fp32 ][ X_last (B,N) fp32 ]

#define BB 256
#define TT 512
#define DD 64
#define NN 512
#define LEAK 0.5f
#define NCTA 128       // 8 m-slabs x 16 n-tiles(32 wide); 1 CTA/SM
#define AS 516         // Asm row stride (words)
#define WBS 1040       // Wb row stride (words)
#define NGRP 8
#define HALF_SZ 8      // CTAs per half-counter (n-tiles 0..7 / 8..15)

typedef unsigned long long ull;

__device__ unsigned g_cnt[NGRP * 2 * 32];    // 128B-spaced half counters
__device__ float g_xt[2][BB][NN];            // tf32-prerounded x_t, double-buffered

__device__ __forceinline__ void fma2(ull &acc, ull a, ull b) {
    asm("fma.rn.f32x2 %0, %1, %2, %0;" : "+l"(acc) : "l"(a), "l"(b));
}
__device__ __forceinline__ float2 unpack2(ull v) {
    float2 r; asm("mov.b64 {%0, %1}, %2;" : "=f"(r.x), "=f"(r.y) : "l"(v)); return r;
}
__device__ __forceinline__ unsigned atom_add_rel(unsigned* p, unsigned v) {
    unsigned r;
    asm volatile("atom.add.release.gpu.global.u32 %0, [%1], %2;"
                 : "=r"(r) : "l"(p), "r"(v) : "memory");
    return r;
}
__device__ __forceinline__ unsigned ld_acq(const unsigned* p) {
    unsigned r;
    asm volatile("ld.acquire.gpu.global.u32 %0, [%1];" : "=r"(r) : "l"(p) : "memory");
    return r;
}
__device__ __forceinline__ float tf32r(float x) {
    unsigned u; asm("cvt.rna.tf32.f32 %0, %1;" : "=r"(u) : "f"(x));
    return __uint_as_float(u);
}
__device__ __forceinline__ void mma8(float &c0, float &c1, float &c2, float &c3,
                                     float a0, float a1, float a2, float a3,
                                     float b0, float b1) {
    asm("mma.sync.aligned.m16n8k8.row.col.f32.tf32.tf32.f32 "
        "{%0,%1,%2,%3},{%4,%5,%6,%7},{%8,%9},{%0,%1,%2,%3};"
        : "+f"(c0), "+f"(c1), "+f"(c2), "+f"(c3)
        : "r"(__float_as_uint(a0)), "r"(__float_as_uint(a1)),
          "r"(__float_as_uint(a2)), "r"(__float_as_uint(a3)),
          "r"(__float_as_uint(b0)), "r"(__float_as_uint(b1)));
}

// ---------------------------------------------------------------------------
// Projection: U = inputs@W_in + b_in; x0 = leak*tanh(U0) at t=0 (also stored
// tf32-rounded into g_xt[0]). Block (0,0) resets the half counters.
// ---------------------------------------------------------------------------
__global__ __launch_bounds__(128) void proj_kernel(
    const float* __restrict__ inp, const float* __restrict__ Win,
    const float* __restrict__ bin, float* __restrict__ X)
{
    __shared__ __align__(16) float Ash[DD][36];
    __shared__ __align__(16) float Wd[DD][64];

    const int tid = threadIdx.x;
    const int m0 = blockIdx.x * 32;
    const int n0 = blockIdx.y * 32;

    if (blockIdx.x == 0 && blockIdx.y == 0 && tid < NGRP * 2)
        g_cnt[tid * 32] = 0u;

    {
        int c = tid & 63, mi = tid >> 6;
        #pragma unroll
        for (int j = 0; j < 16; j++) {
            int m = j * 2 + mi;
            Ash[c][m] = inp[(m0 + m) * DD + c];
        }
    }
    {
        int n = tid & 31, kw = tid >> 5;
        #pragma unroll
        for (int j = 0; j < 16; j++) {
            int k = j * 4 + kw;
            float w = Win[k * NN + n0 + n];
            Wd[k][2 * n] = w; Wd[k][2 * n + 1] = w;
        }
    }
    __syncthreads();

    const int tx = tid & 7;
    const int ty = tid >> 3;
    ull acc0 = 0, acc1 = 0, acc2 = 0, acc3 = 0;

    #pragma unroll
    for (int k = 0; k < DD; k++) {
        ull a = *(const ull*)&Ash[k][2 * ty];
        const ulonglong2* bp = (const ulonglong2*)&Wd[k][8 * tx];
        ulonglong2 b01 = bp[0], b23 = bp[1];
        fma2(acc0, a, b01.x); fma2(acc1, a, b01.y);
        fma2(acc2, a, b23.x); fma2(acc3, a, b23.y);
    }

    const int r0 = m0 + 2 * ty;
    const int t0 = r0 & (TT - 1);
    const int nb = n0 + 4 * tx;
    ull accs[4] = {acc0, acc1, acc2, acc3};
    #pragma unroll
    for (int c = 0; c < 4; c++) {
        float2 v = unpack2(accs[c]);
        int n = nb + c;
        float b = bin[n];
        float u0 = v.x + b;
        float u1 = v.y + b;
        if (t0 == 0) {
            float x0 = LEAK * tanhf(u0);
            X[(size_t)r0 * NN + n] = x0;
            g_xt[0][r0 >> 9][n] = tf32r(x0);
        } else {
            X[(size_t)r0 * NN + n] = u0;
        }
        X[(size_t)(r0 + 1) * NN + n] = u1;
    }
}

// ---------------------------------------------------------------------------
// Persistent tensor-core recurrence: 128 CTAs = 8 m-slabs x 16 n-tiles(32),
// 256 threads = 8 warps = 2 m-halves (wm) x 2 n-halves (wn) x 2 k-halves (kh).
// SPLIT-PHASE: kh=0 group (warps 0-3) polls cntL, stages & GEMMs k [0,256);
//              kh=1 group (warps 4-7) polls cntH, stages & GEMMs k [256,512).
// Groups run independently via named barriers, join at the reduction.
// ---------------------------------------------------------------------------
__global__ __launch_bounds__(256, 1) void esn_mma(
    float* __restrict__ X, const float* __restrict__ Wres,
    const float* __restrict__ bres, float* __restrict__ xlast)
{
    extern __shared__ __align__(16) float smem[];
    float* Asm = smem;                  // [32][AS]
    float* Wb  = smem + 32 * AS;        // [16][WBS] quad-packed tf32 W
    float* Rsm = Wb + 16 * WBS;         // [4][32][8] kh=1 partials

    const int tid  = threadIdx.x;
    const int warp = tid >> 5, lane = tid & 31;
    const int wm   = warp & 1;          // m-half
    const int wn   = (warp >> 1) & 1;   // n-half
    const int kh   = warp >> 2;         // k-half (group id)
    const int gid  = lane >> 2, tig = lane & 3;
    const int bx   = blockIdx.x;
    const int grp  = bx & 7;            // m-slab
    const int nt   = bx >> 3;           // n-tile 0..15
    const int m0   = grp * 32;
    const int n0   = nt * 32;
    const int TN   = TT * NN;

    unsigned* own   = &g_cnt[(grp * 2 + (nt >> 3)) * 32];
    unsigned* mycnt = &g_cnt[(grp * 2 + kh) * 32];

    // ---- stage quad-packed tf32 W once: 16 entries (e = 8*wn + gid) ----
    for (int idx = tid; idx < 16 * 64 * 4; idx += 256) {
        int e   = idx >> 8;             // 0..15
        int rem = idx & 255;
        int k8  = rem >> 2;             // 0..63
        int tg  = rem & 3;
        int k0  = 8 * k8 + tg;
        int nA  = n0 + (e >> 3) * 16 + (e & 7);
        float* d = Wb + e * WBS + k8 * 16 + tg * 4;
        d[0] = tf32r(Wres[(size_t)k0 * NN + nA]);
        d[1] = tf32r(Wres[(size_t)(k0 + 4) * NN + nA]);
        d[2] = tf32r(Wres[(size_t)k0 * NN + nA + 8]);
        d[3] = tf32r(Wres[(size_t)(k0 + 4) * NN + nA + 8]);
    }

    const int r0 = m0 + 16 * wm + gid;          // rows r0, r0+8
    const int cb = n0 + 16 * wn + 2 * tig;      // cols cb,cb+1; +8 for n8=1
    const float* arow0 = Asm + (16 * wm + gid) * AS + kh * 256;
    const float* arow1 = arow0 + 8 * AS;
    const float* wbp = Wb + (wn * 8 + gid) * WBS + kh * 512 + tig * 4;
    float* rme = Rsm + ((size_t)(wm * 2 + wn) * 32 + lane) * 8;

    // staging mapping within each 128-thread group
    const int wprime = warp & 3;             // 0..3 within group
    const int idxg = wprime * 32 + lane;     // 0..127
    const int sr = idxg >> 3;                // rows sr, sr+16
    const int sg = idxg & 7;                 // float4 phase
    const int colbase = kh * 64;             // f4-col offset of this k-half

    const float2 br0 = *(const float2*)&bres[cb];
    const float2 br1 = *(const float2*)&bres[cb + 8];

    float2 p00, p01, p10, p11, u00, u01, u10, u11;
    if (kh == 0) {
        p00 = *(const float2*)&X[(size_t)r0 * TN + cb];
        p01 = *(const float2*)&X[(size_t)r0 * TN + cb + 8];
        p10 = *(const float2*)&X[(size_t)(r0 + 8) * TN + cb];
        p11 = *(const float2*)&X[(size_t)(r0 + 8) * TN + cb + 8];
        size_t b1 = (size_t)r0 * TN + (size_t)1 * NN + cb;
        u00 = __ldcg((const float2*)&X[b1]);
        u01 = __ldcg((const float2*)&X[b1 + 8]);
        u10 = __ldcg((const float2*)&X[b1 + (size_t)8 * TN]);
        u11 = __ldcg((const float2*)&X[b1 + (size_t)8 * TN + 8]);
    }
    __syncthreads();   // Wb ready

    for (int t = 1; t < TT; t++) {
        const int par = (t - 1) & 1;

        // ---- split-phase: poll own k-half, stage own k-half cols ----
        if (wprime == 0 && lane == 0) {
            unsigned target = (unsigned)(t - 1) * HALF_SZ;
            while (ld_acq(mycnt) < target) { }
        }
        asm volatile("bar.sync %0, 128;" :: "r"(1 + kh) : "memory");

        {
            const float4* rp0 = (const float4*)&g_xt[par][m0 + sr][0];
            const float4* rp1 = (const float4*)&g_xt[par][m0 + sr + 16][0];
            float* dr0 = Asm + sr * AS;
            float* dr1 = Asm + (sr + 16) * AS;
            #pragma unroll
            for (int j = 0; j < 8; j++) {
                int i4 = colbase + sg + 8 * j;
                float4 v0 = __ldcg(rp0 + i4);
                float4 v1 = __ldcg(rp1 + i4);
                *(float4*)(dr0 + 4 * i4) = v0;
                *(float4*)(dr1 + 4 * i4) = v1;
            }
        }
        asm volatile("bar.sync %0, 128;" :: "r"(1 + kh) : "memory");

        // ---- GEMM over this warp's k-half (32 k8 chunks) ----
        float h00 = 0.f, h01 = 0.f, h02 = 0.f, h03 = 0.f;
        float h10 = 0.f, h11 = 0.f, h12 = 0.f, h13 = 0.f;
        #pragma unroll 4
        for (int j = 0; j < 32; j++) {
            int kk = j * 8 + tig;
            float a0 = arow0[kk];
            float a2 = arow0[kk + 4];
            float a1 = arow1[kk];
            float a3 = arow1[kk + 4];
            float4 b = *(const float4*)(wbp + j * 16);
            mma8(h00, h01, h02, h03, a0, a1, a2, a3, b.x, b.y);
            mma8(h10, h11, h12, h13, a0, a1, a2, a3, b.z, b.w);
        }

        if (kh == 1) {
            *(float4*)(rme + 0) = make_float4(h00, h01, h02, h03);
            *(float4*)(rme + 4) = make_float4(h10, h11, h12, h13);
        }
        __syncthreads();   // join groups; Rsm ready

        size_t base = (size_t)r0 * TN + (size_t)t * NN + cb;
        float2 o00, o01, o10, o11;
        if (kh == 0) {
            float4 v0 = *(const float4*)(rme + 0);
            float4 v1 = *(const float4*)(rme + 4);
            float s0 = h00 + v0.x, s1 = h01 + v0.y;
            float s2 = h02 + v0.z, s3 = h03 + v0.w;
            float s4 = h10 + v1.x, s5 = h11 + v1.y;
            float s6 = h12 + v1.z, s7 = h13 + v1.w;

            o00.x = 0.5f * p00.x + 0.5f * tanhf(u00.x + s0 + br0.x);
            o00.y = 0.5f * p00.y + 0.5f * tanhf(u00.y + s1 + br0.y);
            o10.x = 0.5f * p10.x + 0.5f * tanhf(u10.x + s2 + br0.x);
            o10.y = 0.5f * p10.y + 0.5f * tanhf(u10.y + s3 + br0.y);
            o01.x = 0.5f * p01.x + 0.5f * tanhf(u01.x + s4 + br1.x);
            o01.y = 0.5f * p01.y + 0.5f * tanhf(u01.y + s5 + br1.y);
            o11.x = 0.5f * p11.x + 0.5f * tanhf(u11.x + s6 + br1.x);
            o11.y = 0.5f * p11.y + 0.5f * tanhf(u11.y + s7 + br1.y);
            p00 = o00; p01 = o01; p10 = o10; p11 = o11;

            // peers only need g_xt -> store it first
            float* xt  = &g_xt[t & 1][r0][cb];
            float* xt8 = &g_xt[t & 1][r0 + 8][cb];
            xt[0]  = tf32r(o00.x); xt[1]  = tf32r(o00.y);
            xt[8]  = tf32r(o01.x); xt[9]  = tf32r(o01.y);
            xt8[0] = tf32r(o10.x); xt8[1] = tf32r(o10.y);
            xt8[8] = tf32r(o11.x); xt8[9] = tf32r(o11.y);
        }

        if (t < TT - 1) {
            __syncthreads();                       // g_xt stores done CTA-wide
            if (tid == 0) atom_add_rel(own, 1u);   // release own half ASAP
            if (kh == 0) {                         // off critical path
                *(float2*)&X[base]                      = o00;
                *(float2*)&X[base + 8]                  = o01;
                *(float2*)&X[base + (size_t)8 * TN]     = o10;
                *(float2*)&X[base + (size_t)8 * TN + 8] = o11;
                size_t bn = base + NN;
                u00 = __ldcg((const float2*)&X[bn]);
                u01 = __ldcg((const float2*)&X[bn + 8]);
                u10 = __ldcg((const float2*)&X[bn + (size_t)8 * TN]);
                u11 = __ldcg((const float2*)&X[bn + (size_t)8 * TN + 8]);
            }
        } else if (kh == 0) {
            *(float2*)&X[base]                      = o00;
            *(float2*)&X[base + 8]                  = o01;
            *(float2*)&X[base + (size_t)8 * TN]     = o10;
            *(float2*)&X[base + (size_t)8 * TN + 8] = o11;
            *(float2*)&xlast[(size_t)r0 * NN + cb]           = o00;
            *(float2*)&xlast[(size_t)r0 * NN + cb + 8]       = o01;
            *(float2*)&xlast[(size_t)(r0 + 8) * NN + cb]     = o10;
            *(float2*)&xlast[(size_t)(r0 + 8) * NN + cb + 8] = o11;
        }
    }
}

extern "C" void kernel_launch(void* const* d_in, const int* in_sizes, int n_in,
                              void* d_out, int out_size)
{
    const float* inp  = (const float*)d_in[0];
    const float* Win  = (const float*)d_in[1];
    const float* bin  = (const float*)d_in[2];
    const float* Wres = (const float*)d_in[3];
    const float* bres = (const float*)d_in[4];

    float* X = (float*)d_out;                       // (B, T, N)
    float* xlast = X + (size_t)BB * TT * NN;        // (B, N)

    const int smem_bytes = (32 * AS + 16 * WBS + 4 * 32 * 8) * sizeof(float);  // 136704
    cudaFuncSetAttribute(esn_mma, cudaFuncAttributeMaxDynamicSharedMemorySize, smem_bytes);

    dim3 g1(BB * TT / 32, NN / 32);
    proj_kernel<<<g1, 128>>>(inp, Win, bin, X);

    esn_mma<<<NCTA, 256, smem_bytes>>>(X, Wres, bres, xlast);
}

// round 13
// speedup vs baseline: 1.9615x; 1.2064x over previous
#include <cuda_runtime.h>
#include <cuda_fp16.h>
#include <math.h>

// ESN: B=256, T=512, D=64, N=512, leak=0.5
// Output: [ X (B,T,N) fp32 ][ X_last (B,N) fp32 ]

#define BB 256
#define TT 512
#define DD 64
#define NN 512
#define LEAK 0.5f
#define NCTA 128       // 8 m-slabs x 16 n-tiles(32 wide); 1 CTA/SM
#define ASH 520        // Asm row stride in halves (1040 B; 260 words mod 32 = 4)
#define WBS32 528      // Wb entry stride in words (132 mod 8 = 4 -> LDS.128 ok)
#define NGRP 8
#define HALF_SZ 8      // CTAs per half-counter

typedef unsigned long long ull;

__device__ unsigned g_cnt[NGRP * 2 * 32];    // 128B-spaced half counters
__device__ __half g_xt[2][BB][NN];           // fp16 x_t, double-buffered (256 KB)

__device__ __forceinline__ void fma2(ull &acc, ull a, ull b) {
    asm("fma.rn.f32x2 %0, %1, %2, %0;" : "+l"(acc) : "l"(a), "l"(b));
}
__device__ __forceinline__ float2 unpack2(ull v) {
    float2 r; asm("mov.b64 {%0, %1}, %2;" : "=f"(r.x), "=f"(r.y) : "l"(v)); return r;
}
__device__ __forceinline__ unsigned atom_add_rel(unsigned* p, unsigned v) {
    unsigned r;
    asm volatile("atom.add.release.gpu.global.u32 %0, [%1], %2;"
                 : "=r"(r) : "l"(p), "r"(v) : "memory");
    return r;
}
__device__ __forceinline__ unsigned ld_acq(const unsigned* p) {
    unsigned r;
    asm volatile("ld.acquire.gpu.global.u32 %0, [%1];" : "=r"(r) : "l"(p) : "memory");
    return r;
}
// fp16 MMA m16n8k16, fp32 accumulate
__device__ __forceinline__ void mma16(float &c0, float &c1, float &c2, float &c3,
                                      unsigned a0, unsigned a1, unsigned a2, unsigned a3,
                                      unsigned b0, unsigned b1) {
    asm("mma.sync.aligned.m16n8k16.row.col.f32.f16.f16.f32 "
        "{%0,%1,%2,%3},{%4,%5,%6,%7},{%8,%9},{%0,%1,%2,%3};"
        : "+f"(c0), "+f"(c1), "+f"(c2), "+f"(c3)
        : "r"(a0), "r"(a1), "r"(a2), "r"(a3), "r"(b0), "r"(b1));
}

// ---------------------------------------------------------------------------
// Projection: U = inputs@W_in + b_in; x0 = leak*tanh(U0) at t=0 (also stored
// fp16 into g_xt[0]). Block (0,0) resets the half counters.
// ---------------------------------------------------------------------------
__global__ __launch_bounds__(128) void proj_kernel(
    const float* __restrict__ inp, const float* __restrict__ Win,
    const float* __restrict__ bin, float* __restrict__ X)
{
    __shared__ __align__(16) float Ash[DD][36];
    __shared__ __align__(16) float Wd[DD][64];

    const int tid = threadIdx.x;
    const int m0 = blockIdx.x * 32;
    const int n0 = blockIdx.y * 32;

    if (blockIdx.x == 0 && blockIdx.y == 0 && tid < NGRP * 2)
        g_cnt[tid * 32] = 0u;

    {
        int c = tid & 63, mi = tid >> 6;
        #pragma unroll
        for (int j = 0; j < 16; j++) {
            int m = j * 2 + mi;
            Ash[c][m] = inp[(m0 + m) * DD + c];
        }
    }
    {
        int n = tid & 31, kw = tid >> 5;
        #pragma unroll
        for (int j = 0; j < 16; j++) {
            int k = j * 4 + kw;
            float w = Win[k * NN + n0 + n];
            Wd[k][2 * n] = w; Wd[k][2 * n + 1] = w;
        }
    }
    __syncthreads();

    const int tx = tid & 7;
    const int ty = tid >> 3;
    ull acc0 = 0, acc1 = 0, acc2 = 0, acc3 = 0;

    #pragma unroll
    for (int k = 0; k < DD; k++) {
        ull a = *(const ull*)&Ash[k][2 * ty];
        const ulonglong2* bp = (const ulonglong2*)&Wd[k][8 * tx];
        ulonglong2 b01 = bp[0], b23 = bp[1];
        fma2(acc0, a, b01.x); fma2(acc1, a, b01.y);
        fma2(acc2, a, b23.x); fma2(acc3, a, b23.y);
    }

    const int r0 = m0 + 2 * ty;
    const int t0 = r0 & (TT - 1);
    const int nb = n0 + 4 * tx;
    ull accs[4] = {acc0, acc1, acc2, acc3};
    #pragma unroll
    for (int c = 0; c < 4; c++) {
        float2 v = unpack2(accs[c]);
        int n = nb + c;
        float b = bin[n];
        float u0 = v.x + b;
        float u1 = v.y + b;
        if (t0 == 0) {
            float x0 = LEAK * tanhf(u0);
            X[(size_t)r0 * NN + n] = x0;
            g_xt[0][r0 >> 9][n] = __float2half_rn(x0);
        } else {
            X[(size_t)r0 * NN + n] = u0;
        }
        X[(size_t)(r0 + 1) * NN + n] = u1;
    }
}

// ---------------------------------------------------------------------------
// Persistent fp16 tensor-core recurrence: 128 CTAs = 8 m-slabs x 16 n-tiles,
// 256 threads = 8 warps = 2 m-halves (wm) x 2 n-halves (wn) x 2 k-halves (kh).
// SPLIT-PHASE: kh groups poll/stage/GEMM independently; join at reduction.
// A fp16 in smem; W fp16 quad-packed (one LDS.128 per k16 per warp).
// ---------------------------------------------------------------------------
__global__ __launch_bounds__(256, 1) void esn_mma(
    float* __restrict__ X, const float* __restrict__ Wres,
    const float* __restrict__ bres, float* __restrict__ xlast)
{
    extern __shared__ __align__(16) char smem[];
    __half* Asm = (__half*)smem;                     // [32][ASH] halves
    float*  Wb  = (float*)(smem + 32 * ASH * 2);     // [16][WBS32] words
    float*  Rsm = Wb + 16 * WBS32;                   // [4][32][8] partials

    const int tid  = threadIdx.x;
    const int warp = tid >> 5, lane = tid & 31;
    const int wm   = warp & 1;          // m-half
    const int wn   = (warp >> 1) & 1;   // n-half
    const int kh   = warp >> 2;         // k-half (group id)
    const int gid  = lane >> 2, tig = lane & 3;
    const int bx   = blockIdx.x;
    const int grp  = bx & 7;            // m-slab
    const int nt   = bx >> 3;           // n-tile 0..15
    const int m0   = grp * 32;
    const int n0   = nt * 32;
    const int TN   = TT * NN;

    unsigned* own   = &g_cnt[(grp * 2 + (nt >> 3)) * 32];
    unsigned* mycnt = &g_cnt[(grp * 2 + kh) * 32];

    // ---- stage quad-packed fp16 W once: 16 entries x 32 k16 x 4 tg ----
    for (int idx = tid; idx < 2048; idx += 256) {
        int e  = idx >> 7;              // 0..15
        int rem = idx & 127;
        int j  = rem >> 2;              // k16 index 0..31
        int tg = rem & 3;
        int k0 = 16 * j + 2 * tg;
        int nA = n0 + (e >> 3) * 16 + (e & 7);
        __half2* d = (__half2*)(Wb + e * WBS32 + j * 16 + tg * 4);
        d[0] = __floats2half2_rn(Wres[(size_t)k0 * NN + nA],
                                 Wres[(size_t)(k0 + 1) * NN + nA]);
        d[1] = __floats2half2_rn(Wres[(size_t)(k0 + 8) * NN + nA],
                                 Wres[(size_t)(k0 + 9) * NN + nA]);
        d[2] = __floats2half2_rn(Wres[(size_t)k0 * NN + nA + 8],
                                 Wres[(size_t)(k0 + 1) * NN + nA + 8]);
        d[3] = __floats2half2_rn(Wres[(size_t)(k0 + 8) * NN + nA + 8],
                                 Wres[(size_t)(k0 + 9) * NN + nA + 8]);
    }

    const int r0 = m0 + 16 * wm + gid;          // rows r0, r0+8
    const int cb = n0 + 16 * wn + 2 * tig;      // cols cb,cb+1; +8 for n8=1
    const __half* arow0 = Asm + (16 * wm + gid) * ASH + kh * 256;
    const __half* arow1 = arow0 + 8 * ASH;
    const float* wbp = Wb + (wn * 8 + gid) * WBS32 + kh * 256 + tig * 4;
    float* rme = Rsm + ((size_t)(wm * 2 + wn) * 32 + lane) * 8;

    // staging mapping within each 128-thread group (rows sr, sr+16)
    const int wprime = warp & 3;
    const int idxg = wprime * 32 + lane;     // 0..127
    const int sr = idxg >> 3;                // 0..15
    const int sg = idxg & 7;                 // f4 phase
    const int colbase = kh * 32;             // f4-col offset of this k-half

    const float2 br0 = *(const float2*)&bres[cb];
    const float2 br1 = *(const float2*)&bres[cb + 8];

    float2 p00, p01, p10, p11, u00, u01, u10, u11;
    if (kh == 0) {
        p00 = *(const float2*)&X[(size_t)r0 * TN + cb];
        p01 = *(const float2*)&X[(size_t)r0 * TN + cb + 8];
        p10 = *(const float2*)&X[(size_t)(r0 + 8) * TN + cb];
        p11 = *(const float2*)&X[(size_t)(r0 + 8) * TN + cb + 8];
        size_t b1 = (size_t)r0 * TN + (size_t)1 * NN + cb;
        u00 = __ldcg((const float2*)&X[b1]);
        u01 = __ldcg((const float2*)&X[b1 + 8]);
        u10 = __ldcg((const float2*)&X[b1 + (size_t)8 * TN]);
        u11 = __ldcg((const float2*)&X[b1 + (size_t)8 * TN + 8]);
    }
    __syncthreads();   // Wb ready

    for (int t = 1; t < TT; t++) {
        const int par = (t - 1) & 1;

        // ---- split-phase: poll own k-half, stage own k-half (fp16) ----
        if (wprime == 0 && lane == 0) {
            unsigned target = (unsigned)(t - 1) * HALF_SZ;
            while (ld_acq(mycnt) < target) { }
        }
        asm volatile("bar.sync %0, 128;" :: "r"(1 + kh) : "memory");

        {
            const float4* rp0 = (const float4*)&g_xt[par][m0 + sr][0];
            const float4* rp1 = (const float4*)&g_xt[par][m0 + sr + 16][0];
            __half* dr0 = Asm + sr * ASH;
            __half* dr1 = Asm + (sr + 16) * ASH;
            #pragma unroll
            for (int j = 0; j < 4; j++) {
                int i4 = colbase + sg + 8 * j;       // f4 index (8 halves each)
                float4 v0 = __ldcg(rp0 + i4);
                float4 v1 = __ldcg(rp1 + i4);
                *(float4*)(dr0 + 8 * i4) = v0;
                *(float4*)(dr1 + 8 * i4) = v1;
            }
        }
        asm volatile("bar.sync %0, 128;" :: "r"(1 + kh) : "memory");

        // ---- GEMM over this warp's k-half: 16 x m16n8k16 pairs ----
        float h00 = 0.f, h01 = 0.f, h02 = 0.f, h03 = 0.f;
        float h10 = 0.f, h11 = 0.f, h12 = 0.f, h13 = 0.f;
        #pragma unroll 4
        for (int j = 0; j < 16; j++) {
            int kk = 16 * j + 2 * tig;
            unsigned a0 = *(const unsigned*)(arow0 + kk);
            unsigned a1 = *(const unsigned*)(arow1 + kk);
            unsigned a2 = *(const unsigned*)(arow0 + kk + 8);
            unsigned a3 = *(const unsigned*)(arow1 + kk + 8);
            uint4 b = *(const uint4*)(wbp + j * 16);
            mma16(h00, h01, h02, h03, a0, a1, a2, a3, b.x, b.y);
            mma16(h10, h11, h12, h13, a0, a1, a2, a3, b.z, b.w);
        }

        if (kh == 1) {
            *(float4*)(rme + 0) = make_float4(h00, h01, h02, h03);
            *(float4*)(rme + 4) = make_float4(h10, h11, h12, h13);
        }
        __syncthreads();   // join groups; Rsm ready

        size_t base = (size_t)r0 * TN + (size_t)t * NN + cb;
        float2 o00, o01, o10, o11;
        if (kh == 0) {
            float4 v0 = *(const float4*)(rme + 0);
            float4 v1 = *(const float4*)(rme + 4);
            float s0 = h00 + v0.x, s1 = h01 + v0.y;
            float s2 = h02 + v0.z, s3 = h03 + v0.w;
            float s4 = h10 + v1.x, s5 = h11 + v1.y;
            float s6 = h12 + v1.z, s7 = h13 + v1.w;

            o00.x = 0.5f * p00.x + 0.5f * tanhf(u00.x + s0 + br0.x);
            o00.y = 0.5f * p00.y + 0.5f * tanhf(u00.y + s1 + br0.y);
            o10.x = 0.5f * p10.x + 0.5f * tanhf(u10.x + s2 + br0.x);
            o10.y = 0.5f * p10.y + 0.5f * tanhf(u10.y + s3 + br0.y);
            o01.x = 0.5f * p01.x + 0.5f * tanhf(u01.x + s4 + br1.x);
            o01.y = 0.5f * p01.y + 0.5f * tanhf(u01.y + s5 + br1.y);
            o11.x = 0.5f * p11.x + 0.5f * tanhf(u11.x + s6 + br1.x);
            o11.y = 0.5f * p11.y + 0.5f * tanhf(u11.y + s7 + br1.y);
            p00 = o00; p01 = o01; p10 = o10; p11 = o11;

            // peers only need g_xt (fp16) -> store it first
            *(__half2*)&g_xt[t & 1][r0][cb]         = __floats2half2_rn(o00.x, o00.y);
            *(__half2*)&g_xt[t & 1][r0][cb + 8]     = __floats2half2_rn(o01.x, o01.y);
            *(__half2*)&g_xt[t & 1][r0 + 8][cb]     = __floats2half2_rn(o10.x, o10.y);
            *(__half2*)&g_xt[t & 1][r0 + 8][cb + 8] = __floats2half2_rn(o11.x, o11.y);
        }

        if (t < TT - 1) {
            __syncthreads();                       // g_xt stores done CTA-wide
            if (tid == 0) atom_add_rel(own, 1u);   // release ASAP
            if (kh == 0) {                         // off critical path
                *(float2*)&X[base]                      = o00;
                *(float2*)&X[base + 8]                  = o01;
                *(float2*)&X[base + (size_t)8 * TN]     = o10;
                *(float2*)&X[base + (size_t)8 * TN + 8] = o11;
                size_t bn = base + NN;
                u00 = __ldcg((const float2*)&X[bn]);
                u01 = __ldcg((const float2*)&X[bn + 8]);
                u10 = __ldcg((const float2*)&X[bn + (size_t)8 * TN]);
                u11 = __ldcg((const float2*)&X[bn + (size_t)8 * TN + 8]);
            }
        } else if (kh == 0) {
            *(float2*)&X[base]                      = o00;
            *(float2*)&X[base + 8]                  = o01;
            *(float2*)&X[base + (size_t)8 * TN]     = o10;
            *(float2*)&X[base + (size_t)8 * TN + 8] = o11;
            *(float2*)&xlast[(size_t)r0 * NN + cb]           = o00;
            *(float2*)&xlast[(size_t)r0 * NN + cb + 8]       = o01;
            *(float2*)&xlast[(size_t)(r0 + 8) * NN + cb]     = o10;
            *(float2*)&xlast[(size_t)(r0 + 8) * NN + cb + 8] = o11;
        }
    }
}

extern "C" void kernel_launch(void* const* d_in, const int* in_sizes, int n_in,
                              void* d_out, int out_size)
{
    const float* inp  = (const float*)d_in[0];
    const float* Win  = (const float*)d_in[1];
    const float* bin  = (const float*)d_in[2];
    const float* Wres = (const float*)d_in[3];
    const float* bres = (const float*)d_in[4];

    float* X = (float*)d_out;                       // (B, T, N)
    float* xlast = X + (size_t)BB * TT * NN;        // (B, N)

    const int smem_bytes = 32 * ASH * 2 + (16 * WBS32 + 4 * 32 * 8) * 4;  // 71168
    cudaFuncSetAttribute(esn_mma, cudaFuncAttributeMaxDynamicSharedMemorySize, smem_bytes);

    dim3 g1(BB * TT / 32, NN / 32);
    proj_kernel<<<g1, 128>>>(inp, Win, bin, X);

    esn_mma<<<NCTA, 256, smem_bytes>>>(X, Wres, bres, xlast);
}

// round 14
// speedup vs baseline: 1.9933x; 1.0162x over previous
#include <cuda_runtime.h>
#include <cuda_fp16.h>
#include <math.h>

// ESN: B=256, T=512, D=64, N=512, leak=0.5
// Output: [ X (B,T,N) fp32 ][ X_last (B,N) fp32 ]

#define BB 256
#define TT 512
#define DD 64
#define NN 512
#define LEAK 0.5f
#define NCTA 128       // 8 m-slabs x 16 n-tiles(32 wide); 1 CTA/SM
#define ASH 520        // Asm row stride in halves
#define WBS32 528      // Wb entry stride in words
#define NGRP 8
#define HALF_SZ 8      // CTAs per half-counter

typedef unsigned long long ull;

__device__ unsigned g_cnt[NGRP * 2 * 32];    // 128B-spaced half counters
__device__ __half g_xt[2][BB][NN];           // fp16 x_t, double-buffered

__device__ __forceinline__ void fma2(ull &acc, ull a, ull b) {
    asm("fma.rn.f32x2 %0, %1, %2, %0;" : "+l"(acc) : "l"(a), "l"(b));
}
__device__ __forceinline__ float2 unpack2(ull v) {
    float2 r; asm("mov.b64 {%0, %1}, %2;" : "=f"(r.x), "=f"(r.y) : "l"(v)); return r;
}
__device__ __forceinline__ unsigned atom_add_rel(unsigned* p, unsigned v) {
    unsigned r;
    asm volatile("atom.add.release.gpu.global.u32 %0, [%1], %2;"
                 : "=r"(r) : "l"(p), "r"(v) : "memory");
    return r;
}
__device__ __forceinline__ unsigned ld_acq(const unsigned* p) {
    unsigned r;
    asm volatile("ld.acquire.gpu.global.u32 %0, [%1];" : "=r"(r) : "l"(p) : "memory");
    return r;
}
__device__ __forceinline__ void mma16(float &c0, float &c1, float &c2, float &c3,
                                      unsigned a0, unsigned a1, unsigned a2, unsigned a3,
                                      unsigned b0, unsigned b1) {
    asm("mma.sync.aligned.m16n8k16.row.col.f32.f16.f16.f32 "
        "{%0,%1,%2,%3},{%4,%5,%6,%7},{%8,%9},{%0,%1,%2,%3};"
        : "+f"(c0), "+f"(c1), "+f"(c2), "+f"(c3)
        : "r"(a0), "r"(a1), "r"(a2), "r"(a3), "r"(b0), "r"(b1));
}

// ---------------------------------------------------------------------------
// Projection: U = inputs@W_in + b_in; x0 = leak*tanh(U0) at t=0 (also fp16
// into g_xt[0]). Block (0,0) resets the half counters.
// ---------------------------------------------------------------------------
__global__ __launch_bounds__(128) void proj_kernel(
    const float* __restrict__ inp, const float* __restrict__ Win,
    const float* __restrict__ bin, float* __restrict__ X)
{
    __shared__ __align__(16) float Ash[DD][36];
    __shared__ __align__(16) float Wd[DD][64];

    const int tid = threadIdx.x;
    const int m0 = blockIdx.x * 32;
    const int n0 = blockIdx.y * 32;

    if (blockIdx.x == 0 && blockIdx.y == 0 && tid < NGRP * 2)
        g_cnt[tid * 32] = 0u;

    {
        int c = tid & 63, mi = tid >> 6;
        #pragma unroll
        for (int j = 0; j < 16; j++) {
            int m = j * 2 + mi;
            Ash[c][m] = inp[(m0 + m) * DD + c];
        }
    }
    {
        int n = tid & 31, kw = tid >> 5;
        #pragma unroll
        for (int j = 0; j < 16; j++) {
            int k = j * 4 + kw;
            float w = Win[k * NN + n0 + n];
            Wd[k][2 * n] = w; Wd[k][2 * n + 1] = w;
        }
    }
    __syncthreads();

    const int tx = tid & 7;
    const int ty = tid >> 3;
    ull acc0 = 0, acc1 = 0, acc2 = 0, acc3 = 0;

    #pragma unroll
    for (int k = 0; k < DD; k++) {
        ull a = *(const ull*)&Ash[k][2 * ty];
        const ulonglong2* bp = (const ulonglong2*)&Wd[k][8 * tx];
        ulonglong2 b01 = bp[0], b23 = bp[1];
        fma2(acc0, a, b01.x); fma2(acc1, a, b01.y);
        fma2(acc2, a, b23.x); fma2(acc3, a, b23.y);
    }

    const int r0 = m0 + 2 * ty;
    const int t0 = r0 & (TT - 1);
    const int nb = n0 + 4 * tx;
    ull accs[4] = {acc0, acc1, acc2, acc3};
    #pragma unroll
    for (int c = 0; c < 4; c++) {
        float2 v = unpack2(accs[c]);
        int n = nb + c;
        float b = bin[n];
        float u0 = v.x + b;
        float u1 = v.y + b;
        if (t0 == 0) {
            float x0 = LEAK * tanhf(u0);
            X[(size_t)r0 * NN + n] = x0;
            g_xt[0][r0 >> 9][n] = __float2half_rn(x0);
        } else {
            X[(size_t)r0 * NN + n] = u0;
        }
        X[(size_t)(r0 + 1) * NN + n] = u1;
    }
}

// ---------------------------------------------------------------------------
// Persistent fp16 tensor-core recurrence, SYMMETRIC epilogue:
// 128 CTAs = 8 m-slabs x 16 n-tiles(32); 8 warps = wm x wn x kh.
// kh groups poll/stage/GEMM their k-half independently; each warp keeps the
// n8-half it owns (kh==n8), exchanges the other via Rsm with warp^4, then
// runs a 4-tanh epilogue on its own 4 outputs. All warps store/prefetch.
// ---------------------------------------------------------------------------
__global__ __launch_bounds__(256, 1) void esn_mma(
    float* __restrict__ X, const float* __restrict__ Wres,
    const float* __restrict__ bres, float* __restrict__ xlast)
{
    extern __shared__ __align__(16) char smem[];
    __half* Asm = (__half*)smem;                     // [32][ASH] halves
    float*  Wb  = (float*)(smem + 32 * ASH * 2);     // [16][WBS32] words
    float*  Rsm = Wb + 16 * WBS32;                   // [8][32][4] exchange

    const int tid  = threadIdx.x;
    const int warp = tid >> 5, lane = tid & 31;
    const int wm   = warp & 1;
    const int wn   = (warp >> 1) & 1;
    const int kh   = warp >> 2;         // k-half / owned n8-half
    const int gid  = lane >> 2, tig = lane & 3;
    const int bx   = blockIdx.x;
    const int grp  = bx & 7;
    const int nt   = bx >> 3;
    const int m0   = grp * 32;
    const int n0   = nt * 32;
    const int TN   = TT * NN;

    unsigned* own   = &g_cnt[(grp * 2 + (nt >> 3)) * 32];
    unsigned* mycnt = &g_cnt[(grp * 2 + kh) * 32];

    // ---- stage quad-packed fp16 W once ----
    for (int idx = tid; idx < 2048; idx += 256) {
        int e  = idx >> 7;
        int rem = idx & 127;
        int j  = rem >> 2;
        int tg = rem & 3;
        int k0 = 16 * j + 2 * tg;
        int nA = n0 + (e >> 3) * 16 + (e & 7);
        __half2* d = (__half2*)(Wb + e * WBS32 + j * 16 + tg * 4);
        d[0] = __floats2half2_rn(Wres[(size_t)k0 * NN + nA],
                                 Wres[(size_t)(k0 + 1) * NN + nA]);
        d[1] = __floats2half2_rn(Wres[(size_t)(k0 + 8) * NN + nA],
                                 Wres[(size_t)(k0 + 9) * NN + nA]);
        d[2] = __floats2half2_rn(Wres[(size_t)k0 * NN + nA + 8],
                                 Wres[(size_t)(k0 + 1) * NN + nA + 8]);
        d[3] = __floats2half2_rn(Wres[(size_t)(k0 + 8) * NN + nA + 8],
                                 Wres[(size_t)(k0 + 9) * NN + nA + 8]);
    }

    const int r0  = m0 + 16 * wm + gid;         // rows r0, r0+8
    const int cb  = n0 + 16 * wn + 2 * tig;     // n8=0 col base
    const int myc = cb + 8 * kh;                // this warp's owned cols
    const __half* arow0 = Asm + (16 * wm + gid) * ASH + kh * 256;
    const __half* arow1 = arow0 + 8 * ASH;
    const float* wbp = Wb + (wn * 8 + gid) * WBS32 + kh * 256 + tig * 4;
    float* rme   = Rsm + (warp * 32 + lane) * 4;
    const float* rpe = Rsm + ((warp ^ 4) * 32 + lane) * 4;

    // staging mapping within each 128-thread group
    const int wprime = warp & 3;
    const int idxg = wprime * 32 + lane;
    const int sr = idxg >> 3;
    const int sg = idxg & 7;
    const int colbase = kh * 32;

    const float2 br = *(const float2*)&bres[myc];

    // register-carried x_prev + U prefetch for t=1 (ALL warps, own cols)
    float2 p0 = *(const float2*)&X[(size_t)r0 * TN + myc];
    float2 p1 = *(const float2*)&X[(size_t)(r0 + 8) * TN + myc];
    float2 u0, u1;
    {
        size_t b1 = (size_t)r0 * TN + (size_t)1 * NN + myc;
        u0 = __ldcg((const float2*)&X[b1]);
        u1 = __ldcg((const float2*)&X[b1 + (size_t)8 * TN]);
    }
    __syncthreads();   // Wb ready

    for (int t = 1; t < TT; t++) {
        const int par = (t - 1) & 1;

        // ---- split-phase: poll own k-half, stage own k-half (fp16) ----
        if (wprime == 0 && lane == 0) {
            unsigned target = (unsigned)(t - 1) * HALF_SZ;
            while (ld_acq(mycnt) < target) { }
        }
        asm volatile("bar.sync %0, 128;" :: "r"(1 + kh) : "memory");

        {
            const float4* rp0 = (const float4*)&g_xt[par][m0 + sr][0];
            const float4* rp1 = (const float4*)&g_xt[par][m0 + sr + 16][0];
            __half* dr0 = Asm + sr * ASH;
            __half* dr1 = Asm + (sr + 16) * ASH;
            #pragma unroll
            for (int j = 0; j < 4; j++) {
                int i4 = colbase + sg + 8 * j;
                float4 v0 = __ldcg(rp0 + i4);
                float4 v1 = __ldcg(rp1 + i4);
                *(float4*)(dr0 + 8 * i4) = v0;
                *(float4*)(dr1 + 8 * i4) = v1;
            }
        }
        asm volatile("bar.sync %0, 128;" :: "r"(1 + kh) : "memory");

        // ---- GEMM over this warp's k-half ----
        float h00 = 0.f, h01 = 0.f, h02 = 0.f, h03 = 0.f;   // n8=0
        float h10 = 0.f, h11 = 0.f, h12 = 0.f, h13 = 0.f;   // n8=1
        #pragma unroll 8
        for (int j = 0; j < 16; j++) {
            int kk = 16 * j + 2 * tig;
            unsigned a0 = *(const unsigned*)(arow0 + kk);
            unsigned a1 = *(const unsigned*)(arow1 + kk);
            unsigned a2 = *(const unsigned*)(arow0 + kk + 8);
            unsigned a3 = *(const unsigned*)(arow1 + kk + 8);
            uint4 b = *(const uint4*)(wbp + j * 16);
            mma16(h00, h01, h02, h03, a0, a1, a2, a3, b.x, b.y);
            mma16(h10, h11, h12, h13, a0, a1, a2, a3, b.z, b.w);
        }

        // ---- symmetric exchange: write the half we do NOT own ----
        if (kh == 0) *(float4*)rme = make_float4(h10, h11, h12, h13);
        else         *(float4*)rme = make_float4(h00, h01, h02, h03);
        __syncthreads();

        float4 pv = *(const float4*)rpe;
        float s0, s1, s2, s3;
        if (kh == 0) { s0 = h00 + pv.x; s1 = h01 + pv.y; s2 = h02 + pv.z; s3 = h03 + pv.w; }
        else         { s0 = h10 + pv.x; s1 = h11 + pv.y; s2 = h12 + pv.z; s3 = h13 + pv.w; }

        // ---- epilogue on own 4 outputs (all 8 warps) ----
        size_t base = (size_t)r0 * TN + (size_t)t * NN + myc;
        float2 o0, o1;
        o0.x = 0.5f * p0.x + 0.5f * tanhf(u0.x + s0 + br.x);
        o0.y = 0.5f * p0.y + 0.5f * tanhf(u0.y + s1 + br.y);
        o1.x = 0.5f * p1.x + 0.5f * tanhf(u1.x + s2 + br.x);
        o1.y = 0.5f * p1.y + 0.5f * tanhf(u1.y + s3 + br.y);
        p0 = o0; p1 = o1;

        // peers only need g_xt (fp16) -> store it first
        *(__half2*)&g_xt[t & 1][r0][myc]     = __floats2half2_rn(o0.x, o0.y);
        *(__half2*)&g_xt[t & 1][r0 + 8][myc] = __floats2half2_rn(o1.x, o1.y);

        if (t < TT - 1) {
            __syncthreads();                       // g_xt stores done CTA-wide
            if (tid == 0) atom_add_rel(own, 1u);   // release ASAP
            // off-critical-path: X stores + next U prefetch overlap the poll
            *(float2*)&X[base]                  = o0;
            *(float2*)&X[base + (size_t)8 * TN] = o1;
            size_t bn = base + NN;
            u0 = __ldcg((const float2*)&X[bn]);
            u1 = __ldcg((const float2*)&X[bn + (size_t)8 * TN]);
        } else {
            *(float2*)&X[base]                  = o0;
            *(float2*)&X[base + (size_t)8 * TN] = o1;
            *(float2*)&xlast[(size_t)r0 * NN + myc]       = o0;
            *(float2*)&xlast[(size_t)(r0 + 8) * NN + myc] = o1;
        }
    }
}

extern "C" void kernel_launch(void* const* d_in, const int* in_sizes, int n_in,
                              void* d_out, int out_size)
{
    const float* inp  = (const float*)d_in[0];
    const float* Win  = (const float*)d_in[1];
    const float* bin  = (const float*)d_in[2];
    const float* Wres = (const float*)d_in[3];
    const float* bres = (const float*)d_in[4];

    float* X = (float*)d_out;                       // (B, T, N)
    float* xlast = X + (size_t)BB * TT * NN;        // (B, N)

    const int smem_bytes = 32 * ASH * 2 + (16 * WBS32 + 8 * 32 * 4) * 4;  // 71168
    cudaFuncSetAttribute(esn_mma, cudaFuncAttributeMaxDynamicSharedMemorySize, smem_bytes);

    dim3 g1(BB * TT / 32, NN / 32);
    proj_kernel<<<g1, 128>>>(inp, Win, bin, X);

    esn_mma<<<NCTA, 256, smem_bytes>>>(X, Wres, bres, xlast);
}